// round 13
// baseline (speedup 1.0000x reference)
#include <cuda_runtime.h>
#include <cstdint>

// Problem constants
#define BSZ 64
#define SL 512
#define EM 1024
#define NH 16
#define HDIM 64
#define QK_SCALE 0.125f   // 1/sqrt(64)

#define SC_STRIDE (BSZ * NH * SL)
#define CW_STRIDE (BSZ * NH * EM)

typedef unsigned long long ull;

__device__ __forceinline__ void ffma2(ull& d, ull a, ull b) {
    asm("fma.rn.f32x2 %0, %1, %2, %0;" : "+l"(d) : "l"(a), "l"(b));
}
__device__ __forceinline__ ull packf2(float x, float y) {
    ull r;
    asm("mov.b64 %0, {%1, %2};" : "=l"(r) : "f"(x), "f"(y));
    return r;
}
__device__ __forceinline__ float lo2(ull v) { return __uint_as_float((unsigned)v); }
__device__ __forceinline__ float hi2(ull v) { return __uint_as_float((unsigned)(v >> 32)); }

// -------- scratch (device globals; no allocations) --------
__device__ float g_qin[BSZ * EM];           // kv_src row at mask_pos
__device__ float g_orig[BSZ * EM];          // model_output row at mask_pos
__device__ float g_q[BSZ * EM];             // scale*(q_in@Wq^T + bq)
__device__ float g_qk[BSZ * NH * EM];       // q_s @ Wk (per head)
__device__ float g_scoresP[4 * SC_STRIDE];  // 4 k-quarter partial scores; attn lands in slice 0
__device__ float g_ctxwP[4 * CW_STRIDE];    // 4 s-quarter partial ctxw
__device__ float g_ctx[BSZ * EM];           // ctxw @ Wv^T + bv
__device__ float g_att[BSZ * EM];           // ctx @ Wout^T + bout

// ================= setup: mask_pos, q_in, origin_q + accumulator init =================
__global__ void k_setup(const float* __restrict__ mo, const float* __restrict__ kno,
                        const int* __restrict__ ids,
                        const int* __restrict__ pmask_id, const int* __restrict__ pknow_id,
                        const float* __restrict__ ipb, const float* __restrict__ opb) {
    __shared__ int smin;
    int b = blockIdx.x, t = threadIdx.x;
    if (t == 0) smin = SL;
    __syncthreads();
    int mid = *pmask_id;
    for (int s = t; s < SL; s += 256)
        if (ids[b * SL + s] == mid) atomicMin(&smin, s);
    __syncthreads();
    int p = (smin < SL) ? smin : 0;   // argmax of all-False -> 0
    bool isk = (ids[b * SL + p] == *pknow_id);
    const float* mrow = mo + (size_t)(b * SL + p) * EM;
    const float* krow = kno + (size_t)b * EM;
    for (int e = t; e < EM; e += 256) {
        float m = mrow[e];
        g_orig[b * EM + e] = m;
        g_qin[b * EM + e]  = isk ? krow[e] : m;
        g_q[b * EM + e]    = QK_SCALE * ipb[e];
        g_ctx[b * EM + e]  = ipb[2 * EM + e];
        g_att[b * EM + e]  = opb[e];
    }
}

// ================= TN GEMM f32x2: C[64 x 1024] += alpha * A[64x1024] @ W[1024x1024]^T
// grid (16 o-tiles, 16 k-splits), k-slice 64.
__global__ __launch_bounds__(256) void k_gemm_tn(const float* __restrict__ W, int mode) {
    __shared__ ull As2[64][33];
    __shared__ ull Ws2[64][33];
    const float* A = mode ? g_ctx : g_qin;
    float* C       = mode ? g_att : g_q;
    float alpha    = mode ? 1.0f : QK_SCALE;
    int o0 = blockIdx.x * 64;
    int kb = blockIdx.y * 64;
    int t = threadIdx.x;
    int lr = t >> 2, lc = (t & 3) << 4;  // 16 floats per thread
    {
        const float* ap = A + (size_t)lr * EM + kb + lc;
        const float* wp = W + (size_t)(o0 + lr) * EM + kb + lc;
#pragma unroll
        for (int j = 0; j < 4; j++) {
            float4 a = *(const float4*)(ap + 4 * j);
            float4 w = *(const float4*)(wp + 4 * j);
            As2[lr][(lc >> 1) + 2 * j]     = packf2(a.x, a.y);
            As2[lr][(lc >> 1) + 2 * j + 1] = packf2(a.z, a.w);
            Ws2[lr][(lc >> 1) + 2 * j]     = packf2(w.x, w.y);
            Ws2[lr][(lc >> 1) + 2 * j + 1] = packf2(w.z, w.w);
        }
    }
    __syncthreads();
    int db = t & 15, bb = t >> 4;
    ull acc[16];
#pragma unroll
    for (int i = 0; i < 16; i++) acc[i] = 0ull;
#pragma unroll 8
    for (int k2 = 0; k2 < 32; k2++) {
        ull av[4], wv[4];
#pragma unroll
        for (int i = 0; i < 4; i++) { av[i] = As2[bb + 16 * i][k2]; wv[i] = Ws2[db + 16 * i][k2]; }
#pragma unroll
        for (int i = 0; i < 4; i++)
#pragma unroll
            for (int j = 0; j < 4; j++) ffma2(acc[i * 4 + j], av[i], wv[j]);
    }
#pragma unroll
    for (int i = 0; i < 4; i++)
#pragma unroll
        for (int j = 0; j < 4; j++)
            atomicAdd(&C[(bb + 16 * i) * EM + o0 + db + 16 * j],
                      alpha * (lo2(acc[i * 4 + j]) + hi2(acc[i * 4 + j])));
}

// ================= ctx = (sum of 4 ctxw partials) @ Wv_h^T per head (f32x2) =================
// grid (16 h, 16 k-splits), k-slice 64.
__global__ __launch_bounds__(256) void k_gemm_ctx(const float* __restrict__ ipw) {
    __shared__ ull As2[64][33];
    __shared__ ull Ws2[64][33];
    int h = blockIdx.x;
    int kb = blockIdx.y * 64;
    const float* A0 = g_ctxwP + h * EM;                      // row stride NH*EM
    const float* W  = ipw + (size_t)(2 * EM + h * HDIM) * EM;
    int t = threadIdx.x;
    int lr = t >> 2, lc = (t & 3) << 4;
    {
        size_t row = (size_t)lr * (NH * EM) + kb + lc;
        float4 s0 = make_float4(0.f, 0.f, 0.f, 0.f);
        float4 s1 = s0, s2 = s0, s3 = s0;
#pragma unroll
        for (int z = 0; z < 4; z++) {
            const float* az = A0 + (size_t)z * CW_STRIDE + row;
            float4 a0 = *(const float4*)(az);
            float4 a1 = *(const float4*)(az + 4);
            float4 a2 = *(const float4*)(az + 8);
            float4 a3 = *(const float4*)(az + 12);
            s0.x += a0.x; s0.y += a0.y; s0.z += a0.z; s0.w += a0.w;
            s1.x += a1.x; s1.y += a1.y; s1.z += a1.z; s1.w += a1.w;
            s2.x += a2.x; s2.y += a2.y; s2.z += a2.z; s2.w += a2.w;
            s3.x += a3.x; s3.y += a3.y; s3.z += a3.z; s3.w += a3.w;
        }
        As2[lr][(lc >> 1)]     = packf2(s0.x, s0.y);
        As2[lr][(lc >> 1) + 1] = packf2(s0.z, s0.w);
        As2[lr][(lc >> 1) + 2] = packf2(s1.x, s1.y);
        As2[lr][(lc >> 1) + 3] = packf2(s1.z, s1.w);
        As2[lr][(lc >> 1) + 4] = packf2(s2.x, s2.y);
        As2[lr][(lc >> 1) + 5] = packf2(s2.z, s2.w);
        As2[lr][(lc >> 1) + 6] = packf2(s3.x, s3.y);
        As2[lr][(lc >> 1) + 7] = packf2(s3.z, s3.w);
        const float* wp = W + (size_t)lr * EM + kb + lc;
#pragma unroll
        for (int j = 0; j < 4; j++) {
            float4 w = *(const float4*)(wp + 4 * j);
            Ws2[lr][(lc >> 1) + 2 * j]     = packf2(w.x, w.y);
            Ws2[lr][(lc >> 1) + 2 * j + 1] = packf2(w.z, w.w);
        }
    }
    __syncthreads();
    int db = t & 15, bb = t >> 4;
    ull acc[16];
#pragma unroll
    for (int i = 0; i < 16; i++) acc[i] = 0ull;
#pragma unroll 8
    for (int k2 = 0; k2 < 32; k2++) {
        ull av[4], wv[4];
#pragma unroll
        for (int i = 0; i < 4; i++) { av[i] = As2[bb + 16 * i][k2]; wv[i] = Ws2[db + 16 * i][k2]; }
#pragma unroll
        for (int i = 0; i < 4; i++)
#pragma unroll
            for (int j = 0; j < 4; j++) ffma2(acc[i * 4 + j], av[i], wv[j]);
    }
#pragma unroll
    for (int i = 0; i < 4; i++)
#pragma unroll
        for (int j = 0; j < 4; j++)
            atomicAdd(&g_ctx[(bb + 16 * i) * EM + h * HDIM + db + 16 * j],
                      lo2(acc[i * 4 + j]) + hi2(acc[i * 4 + j]));
}

// ================= qk[b,h,e] = sum_d q_s[b,h,d] * Wk[h*64+d, e]  (f32x2 over d) =================
// grid (16 e-tiles, 16 heads), 256 thr.
__global__ __launch_bounds__(256) void k_qk(const float* __restrict__ ipw) {
    __shared__ ull As2[64][33];   // [b][d2]
    __shared__ ull Bs2[32][65];   // [d2][e]  (pair of W rows 2d2, 2d2+1)
    int e0 = blockIdx.x * 64;
    int h  = blockIdx.y;
    int t = threadIdx.x;
    // As2: 64 b-rows x 64 d
    {
        int lr = t >> 2, lc = (t & 3) << 4;
        const float* qp = g_q + (size_t)lr * EM + h * HDIM + lc;
#pragma unroll
        for (int j = 0; j < 4; j++) {
            float4 a = *(const float4*)(qp + 4 * j);
            As2[lr][(lc >> 1) + 2 * j]     = packf2(a.x, a.y);
            As2[lr][(lc >> 1) + 2 * j + 1] = packf2(a.z, a.w);
        }
    }
    // Bs2: 32 d2 x 64 e; thread: d2 = t>>3, e8 = (t&7)*8
    {
        int d2 = t >> 3, e8 = (t & 7) << 3;
        const float* w0 = ipw + (size_t)(EM + h * HDIM + 2 * d2) * EM + e0 + e8;
        const float* w1 = w0 + EM;
#pragma unroll
        for (int j = 0; j < 2; j++) {
            float4 a = *(const float4*)(w0 + 4 * j);
            float4 b = *(const float4*)(w1 + 4 * j);
            Bs2[d2][e8 + 4 * j]     = packf2(a.x, b.x);
            Bs2[d2][e8 + 4 * j + 1] = packf2(a.y, b.y);
            Bs2[d2][e8 + 4 * j + 2] = packf2(a.z, b.z);
            Bs2[d2][e8 + 4 * j + 3] = packf2(a.w, b.w);
        }
    }
    __syncthreads();
    int eb = t & 15, bb = t >> 4;
    ull acc[16];
#pragma unroll
    for (int i = 0; i < 16; i++) acc[i] = 0ull;
#pragma unroll 8
    for (int d2 = 0; d2 < 32; d2++) {
        ull av[4], wv[4];
#pragma unroll
        for (int i = 0; i < 4; i++) { av[i] = As2[bb + 16 * i][d2]; wv[i] = Bs2[d2][eb + 16 * i]; }
#pragma unroll
        for (int i = 0; i < 4; i++)
#pragma unroll
            for (int j = 0; j < 4; j++) ffma2(acc[i * 4 + j], av[i], wv[j]);
    }
#pragma unroll
    for (int i = 0; i < 4; i++)
#pragma unroll
        for (int j = 0; j < 4; j++)
            g_qk[((bb + 16 * i) * NH + h) * EM + e0 + eb + 16 * j] =
                lo2(acc[i * 4 + j]) + hi2(acc[i * 4 + j]);
}

// ================= heavy pass 1 (f32x2, packed along k, K-SPLIT x4, COALESCED kv loads) =================
// partial scores over k-quarter z.  grid (64, 4, 4), 128 threads.
__global__ __launch_bounds__(128) void k_scores(const float* __restrict__ mo,
                                                const float* __restrict__ kno,
                                                const int* __restrict__ ids,
                                                const int* __restrict__ pknow_id) {
    __shared__ ull kvs2[128][33];        // [s][k2] packed (k,k+1); 33.8KB
    __shared__ ull qks2[32][18];         // [k2][h] packed (k,k+1); 4.6KB
    __shared__ const float* rowp[128];   // per-row kv source base (knowledge vs model)
    int b = blockIdx.x;
    int s0 = blockIdx.y * 128;
    int kbase = blockIdx.z * (EM / 4);   // k-quarter
    int t = threadIdx.x;
    int kid = *pknow_id;
    rowp[t] = (ids[b * SL + s0 + t] == kid) ? (kno + (size_t)b * EM)
                                            : (mo + (size_t)(b * SL + s0 + t) * EM);
    __syncthreads();

    int hg = (t >> 6) & 1;
    int sp = t & 63;
    ull acc[16];
#pragma unroll
    for (int i = 0; i < 16; i++) acc[i] = 0ull;

    int rr = t >> 4;           // loader: 16 lanes per row -> coalesced 256B segments
    int cc = (t & 15) << 2;    // float column 0..60
    for (int k0 = kbase; k0 < kbase + EM / 4; k0 += 64) {
        // qk tile: 16h x 32k2 (coalesced along k2)
        for (int i = t; i < 512; i += 128) {
            int h = i >> 5, k2 = i & 31;
            qks2[k2][h] = *(const ull*)(g_qk + (size_t)(b * NH + h) * EM + k0 + 2 * k2);
        }
        // kv tile: 128 rows x 64 floats, 16 threads per row (coalesced LDG.128)
#pragma unroll
        for (int i = 0; i < 16; i++) {
            int r = i * 8 + rr;
            float4 v = *(const float4*)(rowp[r] + k0 + cc);
            kvs2[r][(cc >> 1)]     = packf2(v.x, v.y);
            kvs2[r][(cc >> 1) + 1] = packf2(v.z, v.w);
        }
        __syncthreads();
#pragma unroll 8
        for (int k2 = 0; k2 < 32; k2++) {
            ull ka = kvs2[sp][k2];
            ull kb = kvs2[sp + 64][k2];
            ulonglong2 q01 = *(const ulonglong2*)&qks2[k2][hg * 8];
            ulonglong2 q23 = *(const ulonglong2*)&qks2[k2][hg * 8 + 2];
            ulonglong2 q45 = *(const ulonglong2*)&qks2[k2][hg * 8 + 4];
            ulonglong2 q67 = *(const ulonglong2*)&qks2[k2][hg * 8 + 6];
            ffma2(acc[0],  q01.x, ka); ffma2(acc[1],  q01.x, kb);
            ffma2(acc[2],  q01.y, ka); ffma2(acc[3],  q01.y, kb);
            ffma2(acc[4],  q23.x, ka); ffma2(acc[5],  q23.x, kb);
            ffma2(acc[6],  q23.y, ka); ffma2(acc[7],  q23.y, kb);
            ffma2(acc[8],  q45.x, ka); ffma2(acc[9],  q45.x, kb);
            ffma2(acc[10], q45.y, ka); ffma2(acc[11], q45.y, kb);
            ffma2(acc[12], q67.x, ka); ffma2(acc[13], q67.x, kb);
            ffma2(acc[14], q67.y, ka); ffma2(acc[15], q67.y, kb);
        }
        __syncthreads();
    }
    float* outb = g_scoresP + blockIdx.z * SC_STRIDE;
#pragma unroll
    for (int h = 0; h < 8; h++) {
        int row = (b * NH + hg * 8 + h) * SL + s0;
        outb[row + sp]      = lo2(acc[2 * h])     + hi2(acc[2 * h]);
        outb[row + sp + 64] = lo2(acc[2 * h + 1]) + hi2(acc[2 * h + 1]);
    }
}

// ================= softmax over s (512) per (b,h) row; sums the 4 k-quarter partials =================
__global__ void k_softmax() {
    int row = blockIdx.x;
    int t = threadIdx.x;
    float* p = g_scoresP + row * SL;   // slice 0: partial in, attn out
    float v[4];
#pragma unroll
    for (int i = 0; i < 4; i++) {
        int idx = row * SL + t + 128 * i;
        v[i] = g_scoresP[idx] + g_scoresP[SC_STRIDE + idx]
             + g_scoresP[2 * SC_STRIDE + idx] + g_scoresP[3 * SC_STRIDE + idx];
    }
    float m = fmaxf(fmaxf(v[0], v[1]), fmaxf(v[2], v[3]));
#pragma unroll
    for (int o = 16; o; o >>= 1) m = fmaxf(m, __shfl_xor_sync(~0u, m, o));
    __shared__ float red[4];
    if ((t & 31) == 0) red[t >> 5] = m;
    __syncthreads();
    m = fmaxf(fmaxf(red[0], red[1]), fmaxf(red[2], red[3]));
    float s = 0.f;
#pragma unroll
    for (int i = 0; i < 4; i++) { v[i] = __expf(v[i] - m); s += v[i]; }
#pragma unroll
    for (int o = 16; o; o >>= 1) s += __shfl_xor_sync(~0u, s, o);
    __syncthreads();
    if ((t & 31) == 0) red[t >> 5] = s;
    __syncthreads();
    float inv = 1.f / (red[0] + red[1] + red[2] + red[3]);
#pragma unroll
    for (int i = 0; i < 4; i++) p[t + 128 * i] = v[i] * inv;
}

// ================= heavy pass 2 (f32x2, packed along e, S-SPLIT x4) =================
// partial ctxw over s-quarter z.  grid (64, 2, 4), 256 threads.
__global__ __launch_bounds__(256) void k_ctxw(const float* __restrict__ mo,
                                              const float* __restrict__ kno,
                                              const int* __restrict__ ids,
                                              const int* __restrict__ pknow_id) {
    __shared__ ull kvt2[16][257];  // [s][e2] packed (e,e+1); 32.9KB
    __shared__ ull ps2[16][18];    // [s][h] attn duplicated in both lanes
    __shared__ int flag[SL / 4];
    int b = blockIdx.x;
    int e0 = blockIdx.y * 512;
    int sbase = blockIdx.z * (SL / 4);
    int t = threadIdx.x;
    int kid = *pknow_id;
    if (t < SL / 4) flag[t] = (ids[b * SL + sbase + t] == kid) ? 1 : 0;
    __syncthreads();

    int hg = t >> 7;
    int ep = t & 127;
    ull acc[16];
#pragma unroll
    for (int i = 0; i < 16; i++) acc[i] = 0ull;

    for (int sl = 0; sl < SL / 4; sl += 16) {
        int s0 = sbase + sl;
        // attn tile (slice 0 of g_scoresP), duplicated into both f32x2 lanes
        {
            int ss = t >> 4, h = t & 15;
            float v = g_scoresP[(b * NH + h) * SL + s0 + ss];
            unsigned u = __float_as_uint(v);
            ps2[ss][h] = (ull)u | ((ull)u << 32);
        }
        // kv tile: 16 rows x 512 floats; 16 threads per row (coalesced)
        {
            int r = t >> 4, c0 = (t & 15) * 4;
            const float* src = flag[sl + r] ? (kno + (size_t)b * EM)
                                            : (mo + (size_t)(b * SL + s0 + r) * EM);
#pragma unroll
            for (int j = 0; j < 8; j++) {
                int c = c0 + 64 * j;
                float4 v = *(const float4*)(src + e0 + c);
                kvt2[r][c >> 1]       = packf2(v.x, v.y);
                kvt2[r][(c >> 1) + 1] = packf2(v.z, v.w);
            }
        }
        __syncthreads();
#pragma unroll 8
        for (int ss = 0; ss < 16; ss++) {
            ull ka = kvt2[ss][ep];
            ull kb = kvt2[ss][ep + 128];
            ulonglong2 p01 = *(const ulonglong2*)&ps2[ss][hg * 8];
            ulonglong2 p23 = *(const ulonglong2*)&ps2[ss][hg * 8 + 2];
            ulonglong2 p45 = *(const ulonglong2*)&ps2[ss][hg * 8 + 4];
            ulonglong2 p67 = *(const ulonglong2*)&ps2[ss][hg * 8 + 6];
            ffma2(acc[0],  p01.x, ka); ffma2(acc[1],  p01.x, kb);
            ffma2(acc[2],  p01.y, ka); ffma2(acc[3],  p01.y, kb);
            ffma2(acc[4],  p23.x, ka); ffma2(acc[5],  p23.x, kb);
            ffma2(acc[6],  p23.y, ka); ffma2(acc[7],  p23.y, kb);
            ffma2(acc[8],  p45.x, ka); ffma2(acc[9],  p45.x, kb);
            ffma2(acc[10], p45.y, ka); ffma2(acc[11], p45.y, kb);
            ffma2(acc[12], p67.x, ka); ffma2(acc[13], p67.x, kb);
            ffma2(acc[14], p67.y, ka); ffma2(acc[15], p67.y, kb);
        }
        __syncthreads();
    }
    float* outb = g_ctxwP + blockIdx.z * CW_STRIDE;
#pragma unroll
    for (int h = 0; h < 8; h++) {
        size_t g = (size_t)(b * NH + hg * 8 + h) * EM + e0;
        *(ull*)&outb[g + 2 * ep]         = acc[2 * h];
        *(ull*)&outb[g + 2 * (ep + 128)] = acc[2 * h + 1];
    }
}

// ================= final combine (+ robust bool-dtype detection) =================
__global__ void k_combine(const unsigned char* __restrict__ emk,
                          const float* __restrict__ strength,
                          float* __restrict__ out) {
    __shared__ int mode;  // 0=int32, 1=uint8, 2=float32
    int b = blockIdx.x, t = threadIdx.x;
    if (t == 0) {
        const unsigned* pw = (const unsigned*)emk;
        int isf = 0, isu = 0;
        for (int w = 0; w < 16; ++w) if (pw[w] == 0x3F800000u) isf = 1;
        if (!isf)
            for (int j = 0; j < 64; ++j) if ((j & 3) && emk[j]) isu = 1;
        mode = isf ? 2 : (isu ? 1 : 0);
    }
    __syncthreads();
    bool empty;
    if (mode == 1)      empty = emk[b] != 0;
    else if (mode == 2) empty = ((const unsigned*)emk)[b] != 0;
    else                empty = ((const int*)emk)[b] != 0;
    float st = *strength;
    for (int o = t; o < EM; o += 256) {
        float og = g_orig[b * EM + o];
        out[b * EM + o] = empty ? og : og + st * g_att[b * EM + o];
    }
}

extern "C" void kernel_launch(void* const* d_in, const int* in_sizes, int n_in,
                              void* d_out, int out_size) {
    const float* mo       = (const float*)d_in[0];
    const float* kno      = (const float*)d_in[1];
    const float* ipw      = (const float*)d_in[2];
    const float* ipb      = (const float*)d_in[3];
    const float* opw      = (const float*)d_in[4];
    const float* opb      = (const float*)d_in[5];
    const float* strength = (const float*)d_in[6];
    const int*   ids      = (const int*)d_in[7];
    const unsigned char* emk = (const unsigned char*)d_in[8];
    const int*   kid      = (const int*)d_in[9];
    const int*   midp     = (const int*)d_in[10];
    float* out = (float*)d_out;

    k_setup<<<64, 256>>>(mo, kno, ids, midp, kid, ipb, opb);
    k_gemm_tn<<<dim3(16, 16), 256>>>(ipw, 0);           // q = scale*(q_in@Wq^T + bq)
    k_qk<<<dim3(16, 16), 256>>>(ipw);                   // qk = q_s @ Wk per head
    k_scores<<<dim3(64, 4, 4), 128>>>(mo, kno, ids, kid);
    k_softmax<<<BSZ * NH, 128>>>();
    k_ctxw<<<dim3(64, 2, 4), 256>>>(mo, kno, ids, kid);
    k_gemm_ctx<<<dim3(16, 16), 256>>>(ipw);             // ctx = (Σ ctxwP)@Wv^T + bv
    k_gemm_tn<<<dim3(16, 16), 256>>>(opw, 1);           // att = ctx@Wout^T + bout
    k_combine<<<64, 256>>>(emk, strength, out);
}

// round 15
// speedup vs baseline: 1.2882x; 1.2882x over previous
#include <cuda_runtime.h>
#include <cstdint>

// Problem constants
#define BSZ 64
#define SL 512
#define EM 1024
#define NH 16
#define HDIM 64
#define QK_SCALE 0.125f   // 1/sqrt(64)

#define SC_STRIDE (BSZ * NH * SL)
#define CW_STRIDE (BSZ * NH * EM)

typedef unsigned long long ull;

__device__ __forceinline__ void ffma2(ull& d, ull a, ull b) {
    asm("fma.rn.f32x2 %0, %1, %2, %0;" : "+l"(d) : "l"(a), "l"(b));
}
__device__ __forceinline__ ull packf2(float x, float y) {
    ull r;
    asm("mov.b64 %0, {%1, %2};" : "=l"(r) : "f"(x), "f"(y));
    return r;
}
__device__ __forceinline__ float lo2(ull v) { return __uint_as_float((unsigned)v); }
__device__ __forceinline__ float hi2(ull v) { return __uint_as_float((unsigned)(v >> 32)); }

// -------- scratch (device globals; no allocations) --------
__device__ float g_qin[BSZ * EM];           // kv_src row at mask_pos
__device__ float g_orig[BSZ * EM];          // model_output row at mask_pos
__device__ float g_q[BSZ * EM];             // scale*(q_in@Wq^T + bq)
__device__ float g_qk[BSZ * NH * EM];       // q_s @ Wk (per head)
__device__ float g_scoresP[4 * SC_STRIDE];  // 4 k-quarter partial scores; attn lands in slice 0
__device__ float g_ctxwP[4 * CW_STRIDE];    // 4 s-quarter partial ctxw
__device__ float g_ctx[BSZ * EM];           // ctxw @ Wv^T + bv
__device__ float g_att[BSZ * EM];           // ctx @ Wout^T + bout

// ================= setup: mask_pos, q_in, origin_q + accumulator init =================
__global__ void k_setup(const float* __restrict__ mo, const float* __restrict__ kno,
                        const int* __restrict__ ids,
                        const int* __restrict__ pmask_id, const int* __restrict__ pknow_id,
                        const float* __restrict__ ipb, const float* __restrict__ opb) {
    __shared__ int smin;
    int b = blockIdx.x, t = threadIdx.x;
    if (t == 0) smin = SL;
    __syncthreads();
    int mid = *pmask_id;
    for (int s = t; s < SL; s += 256)
        if (ids[b * SL + s] == mid) atomicMin(&smin, s);
    __syncthreads();
    int p = (smin < SL) ? smin : 0;   // argmax of all-False -> 0
    bool isk = (ids[b * SL + p] == *pknow_id);
    const float* mrow = mo + (size_t)(b * SL + p) * EM;
    const float* krow = kno + (size_t)b * EM;
    for (int e = t; e < EM; e += 256) {
        float m = mrow[e];
        g_orig[b * EM + e] = m;
        g_qin[b * EM + e]  = isk ? krow[e] : m;
        g_q[b * EM + e]    = QK_SCALE * ipb[e];
        g_ctx[b * EM + e]  = ipb[2 * EM + e];
        g_att[b * EM + e]  = opb[e];
    }
}

// ================= TN GEMM f32x2: C[64 x 1024] += alpha * A[64x1024] @ W[1024x1024]^T
// grid (16 o-tiles, 16 k-splits), k-slice 64.
__global__ __launch_bounds__(256) void k_gemm_tn(const float* __restrict__ W, int mode) {
    __shared__ ull As2[64][33];
    __shared__ ull Ws2[64][33];
    const float* A = mode ? g_ctx : g_qin;
    float* C       = mode ? g_att : g_q;
    float alpha    = mode ? 1.0f : QK_SCALE;
    int o0 = blockIdx.x * 64;
    int kb = blockIdx.y * 64;
    int t = threadIdx.x;
    int lr = t >> 2, lc = (t & 3) << 4;  // 16 floats per thread
    {
        const float* ap = A + (size_t)lr * EM + kb + lc;
        const float* wp = W + (size_t)(o0 + lr) * EM + kb + lc;
#pragma unroll
        for (int j = 0; j < 4; j++) {
            float4 a = *(const float4*)(ap + 4 * j);
            float4 w = *(const float4*)(wp + 4 * j);
            As2[lr][(lc >> 1) + 2 * j]     = packf2(a.x, a.y);
            As2[lr][(lc >> 1) + 2 * j + 1] = packf2(a.z, a.w);
            Ws2[lr][(lc >> 1) + 2 * j]     = packf2(w.x, w.y);
            Ws2[lr][(lc >> 1) + 2 * j + 1] = packf2(w.z, w.w);
        }
    }
    __syncthreads();
    int db = t & 15, bb = t >> 4;
    ull acc[16];
#pragma unroll
    for (int i = 0; i < 16; i++) acc[i] = 0ull;
#pragma unroll 8
    for (int k2 = 0; k2 < 32; k2++) {
        ull av[4], wv[4];
#pragma unroll
        for (int i = 0; i < 4; i++) { av[i] = As2[bb + 16 * i][k2]; wv[i] = Ws2[db + 16 * i][k2]; }
#pragma unroll
        for (int i = 0; i < 4; i++)
#pragma unroll
            for (int j = 0; j < 4; j++) ffma2(acc[i * 4 + j], av[i], wv[j]);
    }
#pragma unroll
    for (int i = 0; i < 4; i++)
#pragma unroll
        for (int j = 0; j < 4; j++)
            atomicAdd(&C[(bb + 16 * i) * EM + o0 + db + 16 * j],
                      alpha * (lo2(acc[i * 4 + j]) + hi2(acc[i * 4 + j])));
}

// ================= ctx = (sum of 4 ctxw partials) @ Wv_h^T per head (f32x2) =================
// grid (16 h, 16 k-splits), k-slice 64.
__global__ __launch_bounds__(256) void k_gemm_ctx(const float* __restrict__ ipw) {
    __shared__ ull As2[64][33];
    __shared__ ull Ws2[64][33];
    int h = blockIdx.x;
    int kb = blockIdx.y * 64;
    const float* A0 = g_ctxwP + h * EM;                      // row stride NH*EM
    const float* W  = ipw + (size_t)(2 * EM + h * HDIM) * EM;
    int t = threadIdx.x;
    int lr = t >> 2, lc = (t & 3) << 4;
    {
        size_t row = (size_t)lr * (NH * EM) + kb + lc;
        float4 s0 = make_float4(0.f, 0.f, 0.f, 0.f);
        float4 s1 = s0, s2 = s0, s3 = s0;
#pragma unroll
        for (int z = 0; z < 4; z++) {
            const float* az = A0 + (size_t)z * CW_STRIDE + row;
            float4 a0 = *(const float4*)(az);
            float4 a1 = *(const float4*)(az + 4);
            float4 a2 = *(const float4*)(az + 8);
            float4 a3 = *(const float4*)(az + 12);
            s0.x += a0.x; s0.y += a0.y; s0.z += a0.z; s0.w += a0.w;
            s1.x += a1.x; s1.y += a1.y; s1.z += a1.z; s1.w += a1.w;
            s2.x += a2.x; s2.y += a2.y; s2.z += a2.z; s2.w += a2.w;
            s3.x += a3.x; s3.y += a3.y; s3.z += a3.z; s3.w += a3.w;
        }
        As2[lr][(lc >> 1)]     = packf2(s0.x, s0.y);
        As2[lr][(lc >> 1) + 1] = packf2(s0.z, s0.w);
        As2[lr][(lc >> 1) + 2] = packf2(s1.x, s1.y);
        As2[lr][(lc >> 1) + 3] = packf2(s1.z, s1.w);
        As2[lr][(lc >> 1) + 4] = packf2(s2.x, s2.y);
        As2[lr][(lc >> 1) + 5] = packf2(s2.z, s2.w);
        As2[lr][(lc >> 1) + 6] = packf2(s3.x, s3.y);
        As2[lr][(lc >> 1) + 7] = packf2(s3.z, s3.w);
        const float* wp = W + (size_t)lr * EM + kb + lc;
#pragma unroll
        for (int j = 0; j < 4; j++) {
            float4 w = *(const float4*)(wp + 4 * j);
            Ws2[lr][(lc >> 1) + 2 * j]     = packf2(w.x, w.y);
            Ws2[lr][(lc >> 1) + 2 * j + 1] = packf2(w.z, w.w);
        }
    }
    __syncthreads();
    int db = t & 15, bb = t >> 4;
    ull acc[16];
#pragma unroll
    for (int i = 0; i < 16; i++) acc[i] = 0ull;
#pragma unroll 8
    for (int k2 = 0; k2 < 32; k2++) {
        ull av[4], wv[4];
#pragma unroll
        for (int i = 0; i < 4; i++) { av[i] = As2[bb + 16 * i][k2]; wv[i] = Ws2[db + 16 * i][k2]; }
#pragma unroll
        for (int i = 0; i < 4; i++)
#pragma unroll
            for (int j = 0; j < 4; j++) ffma2(acc[i * 4 + j], av[i], wv[j]);
    }
#pragma unroll
    for (int i = 0; i < 4; i++)
#pragma unroll
        for (int j = 0; j < 4; j++)
            atomicAdd(&g_ctx[(bb + 16 * i) * EM + h * HDIM + db + 16 * j],
                      lo2(acc[i * 4 + j]) + hi2(acc[i * 4 + j]));
}

// ================= qk[b,h,e] = sum_d q_s[b,h,d] * Wk[h*64+d, e]  (f32x2 over d) =================
// grid (16 e-tiles, 16 heads), 256 thr.
__global__ __launch_bounds__(256) void k_qk(const float* __restrict__ ipw) {
    __shared__ ull As2[64][33];   // [b][d2]
    __shared__ ull Bs2[32][65];   // [d2][e]  (pair of W rows 2d2, 2d2+1)
    int e0 = blockIdx.x * 64;
    int h  = blockIdx.y;
    int t = threadIdx.x;
    // As2: 64 b-rows x 64 d
    {
        int lr = t >> 2, lc = (t & 3) << 4;
        const float* qp = g_q + (size_t)lr * EM + h * HDIM + lc;
#pragma unroll
        for (int j = 0; j < 4; j++) {
            float4 a = *(const float4*)(qp + 4 * j);
            As2[lr][(lc >> 1) + 2 * j]     = packf2(a.x, a.y);
            As2[lr][(lc >> 1) + 2 * j + 1] = packf2(a.z, a.w);
        }
    }
    // Bs2: 32 d2 x 64 e; thread: d2 = t>>3, e8 = (t&7)*8
    {
        int d2 = t >> 3, e8 = (t & 7) << 3;
        const float* w0 = ipw + (size_t)(EM + h * HDIM + 2 * d2) * EM + e0 + e8;
        const float* w1 = w0 + EM;
#pragma unroll
        for (int j = 0; j < 2; j++) {
            float4 a = *(const float4*)(w0 + 4 * j);
            float4 b = *(const float4*)(w1 + 4 * j);
            Bs2[d2][e8 + 4 * j]     = packf2(a.x, b.x);
            Bs2[d2][e8 + 4 * j + 1] = packf2(a.y, b.y);
            Bs2[d2][e8 + 4 * j + 2] = packf2(a.z, b.z);
            Bs2[d2][e8 + 4 * j + 3] = packf2(a.w, b.w);
        }
    }
    __syncthreads();
    int eb = t & 15, bb = t >> 4;
    ull acc[16];
#pragma unroll
    for (int i = 0; i < 16; i++) acc[i] = 0ull;
#pragma unroll 8
    for (int d2 = 0; d2 < 32; d2++) {
        ull av[4], wv[4];
#pragma unroll
        for (int i = 0; i < 4; i++) { av[i] = As2[bb + 16 * i][d2]; wv[i] = Bs2[d2][eb + 16 * i]; }
#pragma unroll
        for (int i = 0; i < 4; i++)
#pragma unroll
            for (int j = 0; j < 4; j++) ffma2(acc[i * 4 + j], av[i], wv[j]);
    }
#pragma unroll
    for (int i = 0; i < 4; i++)
#pragma unroll
        for (int j = 0; j < 4; j++)
            g_qk[((bb + 16 * i) * NH + h) * EM + e0 + eb + 16 * j] =
                lo2(acc[i * 4 + j]) + hi2(acc[i * 4 + j]);
}

// ================= heavy pass 1 (f32x2, packed along k, K-SPLIT x4) =================
// COALESCED kv loads with REGISTER-ONLY address generation (16-bit row bitmask).
// partial scores over k-quarter z.  grid (64, 4, 4), 128 threads.
__global__ __launch_bounds__(128) void k_scores(const float* __restrict__ mo,
                                                const float* __restrict__ kno,
                                                const int* __restrict__ ids,
                                                const int* __restrict__ pknow_id) {
    __shared__ ull kvs2[128][33];  // [s][k2] packed (k,k+1); 33.8KB
    __shared__ ull qks2[32][18];   // [k2][h] packed (k,k+1); 4.6KB
    int b = blockIdx.x;
    int s0 = blockIdx.y * 128;
    int kbase = blockIdx.z * (EM / 4);   // k-quarter
    int t = threadIdx.x;
    int kid = *pknow_id;

    int hg = (t >> 6) & 1;
    int sp = t & 63;
    ull acc[16];
#pragma unroll
    for (int i = 0; i < 16; i++) acc[i] = 0ull;

    // Loader assignment: 16 lanes per row; thread covers rows r = i*8 + rr.
    int rr = t >> 4;           // 0..7
    int cc = (t & 15) << 2;    // float column 0..60
    const float* knoB = kno + (size_t)b * EM;
    const float* moB  = mo + (size_t)(b * SL + s0) * EM;   // + r*EM per row
    unsigned mask = 0;
#pragma unroll
    for (int i = 0; i < 16; i++)
        if (ids[b * SL + s0 + i * 8 + rr] == kid) mask |= (1u << i);

    for (int k0 = kbase; k0 < kbase + EM / 4; k0 += 64) {
        // qk tile: 16h x 32k2 (coalesced along k2)
        for (int i = t; i < 512; i += 128) {
            int h = i >> 5, k2 = i & 31;
            qks2[k2][h] = *(const ull*)(g_qk + (size_t)(b * NH + h) * EM + k0 + 2 * k2);
        }
        // kv tile: 128 rows x 64 floats, 16 threads per row (coalesced LDG.128, reg addresses)
#pragma unroll
        for (int i = 0; i < 16; i++) {
            int r = i * 8 + rr;
            const float* src = (mask & (1u << i)) ? knoB : (moB + (size_t)r * EM);
            float4 v = *(const float4*)(src + k0 + cc);
            kvs2[r][(cc >> 1)]     = packf2(v.x, v.y);
            kvs2[r][(cc >> 1) + 1] = packf2(v.z, v.w);
        }
        __syncthreads();
#pragma unroll 8
        for (int k2 = 0; k2 < 32; k2++) {
            ull ka = kvs2[sp][k2];
            ull kb = kvs2[sp + 64][k2];
            ulonglong2 q01 = *(const ulonglong2*)&qks2[k2][hg * 8];
            ulonglong2 q23 = *(const ulonglong2*)&qks2[k2][hg * 8 + 2];
            ulonglong2 q45 = *(const ulonglong2*)&qks2[k2][hg * 8 + 4];
            ulonglong2 q67 = *(const ulonglong2*)&qks2[k2][hg * 8 + 6];
            ffma2(acc[0],  q01.x, ka); ffma2(acc[1],  q01.x, kb);
            ffma2(acc[2],  q01.y, ka); ffma2(acc[3],  q01.y, kb);
            ffma2(acc[4],  q23.x, ka); ffma2(acc[5],  q23.x, kb);
            ffma2(acc[6],  q23.y, ka); ffma2(acc[7],  q23.y, kb);
            ffma2(acc[8],  q45.x, ka); ffma2(acc[9],  q45.x, kb);
            ffma2(acc[10], q45.y, ka); ffma2(acc[11], q45.y, kb);
            ffma2(acc[12], q67.x, ka); ffma2(acc[13], q67.x, kb);
            ffma2(acc[14], q67.y, ka); ffma2(acc[15], q67.y, kb);
        }
        __syncthreads();
    }
    float* outb = g_scoresP + blockIdx.z * SC_STRIDE;
#pragma unroll
    for (int h = 0; h < 8; h++) {
        int row = (b * NH + hg * 8 + h) * SL + s0;
        outb[row + sp]      = lo2(acc[2 * h])     + hi2(acc[2 * h]);
        outb[row + sp + 64] = lo2(acc[2 * h + 1]) + hi2(acc[2 * h + 1]);
    }
}

// ================= softmax over s (512) per (b,h) row; sums the 4 k-quarter partials =================
__global__ void k_softmax() {
    int row = blockIdx.x;
    int t = threadIdx.x;
    float* p = g_scoresP + row * SL;   // slice 0: partial in, attn out
    float v[4];
#pragma unroll
    for (int i = 0; i < 4; i++) {
        int idx = row * SL + t + 128 * i;
        v[i] = g_scoresP[idx] + g_scoresP[SC_STRIDE + idx]
             + g_scoresP[2 * SC_STRIDE + idx] + g_scoresP[3 * SC_STRIDE + idx];
    }
    float m = fmaxf(fmaxf(v[0], v[1]), fmaxf(v[2], v[3]));
#pragma unroll
    for (int o = 16; o; o >>= 1) m = fmaxf(m, __shfl_xor_sync(~0u, m, o));
    __shared__ float red[4];
    if ((t & 31) == 0) red[t >> 5] = m;
    __syncthreads();
    m = fmaxf(fmaxf(red[0], red[1]), fmaxf(red[2], red[3]));
    float s = 0.f;
#pragma unroll
    for (int i = 0; i < 4; i++) { v[i] = __expf(v[i] - m); s += v[i]; }
#pragma unroll
    for (int o = 16; o; o >>= 1) s += __shfl_xor_sync(~0u, s, o);
    __syncthreads();
    if ((t & 31) == 0) red[t >> 5] = s;
    __syncthreads();
    float inv = 1.f / (red[0] + red[1] + red[2] + red[3]);
#pragma unroll
    for (int i = 0; i < 4; i++) p[t + 128 * i] = v[i] * inv;
}

// ================= heavy pass 2 (f32x2, packed along e, S-SPLIT x4) =================
// partial ctxw over s-quarter z.  grid (64, 2, 4), 256 threads.
__global__ __launch_bounds__(256) void k_ctxw(const float* __restrict__ mo,
                                              const float* __restrict__ kno,
                                              const int* __restrict__ ids,
                                              const int* __restrict__ pknow_id) {
    __shared__ ull kvt2[16][257];  // [s][e2] packed (e,e+1); 32.9KB
    __shared__ ull ps2[16][18];    // [s][h] attn duplicated in both lanes
    __shared__ int flag[SL / 4];
    int b = blockIdx.x;
    int e0 = blockIdx.y * 512;
    int sbase = blockIdx.z * (SL / 4);
    int t = threadIdx.x;
    int kid = *pknow_id;
    if (t < SL / 4) flag[t] = (ids[b * SL + sbase + t] == kid) ? 1 : 0;
    __syncthreads();

    int hg = t >> 7;
    int ep = t & 127;
    ull acc[16];
#pragma unroll
    for (int i = 0; i < 16; i++) acc[i] = 0ull;

    for (int sl = 0; sl < SL / 4; sl += 16) {
        int s0 = sbase + sl;
        // attn tile (slice 0 of g_scoresP), duplicated into both f32x2 lanes
        {
            int ss = t >> 4, h = t & 15;
            float v = g_scoresP[(b * NH + h) * SL + s0 + ss];
            unsigned u = __float_as_uint(v);
            ps2[ss][h] = (ull)u | ((ull)u << 32);
        }
        // kv tile: 16 rows x 512 floats; 16 threads per row (coalesced)
        {
            int r = t >> 4, c0 = (t & 15) * 4;
            const float* src = flag[sl + r] ? (kno + (size_t)b * EM)
                                            : (mo + (size_t)(b * SL + s0 + r) * EM);
#pragma unroll
            for (int j = 0; j < 8; j++) {
                int c = c0 + 64 * j;
                float4 v = *(const float4*)(src + e0 + c);
                kvt2[r][c >> 1]       = packf2(v.x, v.y);
                kvt2[r][(c >> 1) + 1] = packf2(v.z, v.w);
            }
        }
        __syncthreads();
#pragma unroll 8
        for (int ss = 0; ss < 16; ss++) {
            ull ka = kvt2[ss][ep];
            ull kb = kvt2[ss][ep + 128];
            ulonglong2 p01 = *(const ulonglong2*)&ps2[ss][hg * 8];
            ulonglong2 p23 = *(const ulonglong2*)&ps2[ss][hg * 8 + 2];
            ulonglong2 p45 = *(const ulonglong2*)&ps2[ss][hg * 8 + 4];
            ulonglong2 p67 = *(const ulonglong2*)&ps2[ss][hg * 8 + 6];
            ffma2(acc[0],  p01.x, ka); ffma2(acc[1],  p01.x, kb);
            ffma2(acc[2],  p01.y, ka); ffma2(acc[3],  p01.y, kb);
            ffma2(acc[4],  p23.x, ka); ffma2(acc[5],  p23.x, kb);
            ffma2(acc[6],  p23.y, ka); ffma2(acc[7],  p23.y, kb);
            ffma2(acc[8],  p45.x, ka); ffma2(acc[9],  p45.x, kb);
            ffma2(acc[10], p45.y, ka); ffma2(acc[11], p45.y, kb);
            ffma2(acc[12], p67.x, ka); ffma2(acc[13], p67.x, kb);
            ffma2(acc[14], p67.y, ka); ffma2(acc[15], p67.y, kb);
        }
        __syncthreads();
    }
    float* outb = g_ctxwP + blockIdx.z * CW_STRIDE;
#pragma unroll
    for (int h = 0; h < 8; h++) {
        size_t g = (size_t)(b * NH + hg * 8 + h) * EM + e0;
        *(ull*)&outb[g + 2 * ep]         = acc[2 * h];
        *(ull*)&outb[g + 2 * (ep + 128)] = acc[2 * h + 1];
    }
}

// ================= final combine (+ robust bool-dtype detection) =================
__global__ void k_combine(const unsigned char* __restrict__ emk,
                          const float* __restrict__ strength,
                          float* __restrict__ out) {
    __shared__ int mode;  // 0=int32, 1=uint8, 2=float32
    int b = blockIdx.x, t = threadIdx.x;
    if (t == 0) {
        const unsigned* pw = (const unsigned*)emk;
        int isf = 0, isu = 0;
        for (int w = 0; w < 16; ++w) if (pw[w] == 0x3F800000u) isf = 1;
        if (!isf)
            for (int j = 0; j < 64; ++j) if ((j & 3) && emk[j]) isu = 1;
        mode = isf ? 2 : (isu ? 1 : 0);
    }
    __syncthreads();
    bool empty;
    if (mode == 1)      empty = emk[b] != 0;
    else if (mode == 2) empty = ((const unsigned*)emk)[b] != 0;
    else                empty = ((const int*)emk)[b] != 0;
    float st = *strength;
    for (int o = t; o < EM; o += 256) {
        float og = g_orig[b * EM + o];
        out[b * EM + o] = empty ? og : og + st * g_att[b * EM + o];
    }
}

extern "C" void kernel_launch(void* const* d_in, const int* in_sizes, int n_in,
                              void* d_out, int out_size) {
    const float* mo       = (const float*)d_in[0];
    const float* kno      = (const float*)d_in[1];
    const float* ipw      = (const float*)d_in[2];
    const float* ipb      = (const float*)d_in[3];
    const float* opw      = (const float*)d_in[4];
    const float* opb      = (const float*)d_in[5];
    const float* strength = (const float*)d_in[6];
    const int*   ids      = (const int*)d_in[7];
    const unsigned char* emk = (const unsigned char*)d_in[8];
    const int*   kid      = (const int*)d_in[9];
    const int*   midp     = (const int*)d_in[10];
    float* out = (float*)d_out;

    k_setup<<<64, 256>>>(mo, kno, ids, midp, kid, ipb, opb);
    k_gemm_tn<<<dim3(16, 16), 256>>>(ipw, 0);           // q = scale*(q_in@Wq^T + bq)
    k_qk<<<dim3(16, 16), 256>>>(ipw);                   // qk = q_s @ Wk per head
    k_scores<<<dim3(64, 4, 4), 128>>>(mo, kno, ids, kid);
    k_softmax<<<BSZ * NH, 128>>>();
    k_ctxw<<<dim3(64, 2, 4), 256>>>(mo, kno, ids, kid);
    k_gemm_ctx<<<dim3(16, 16), 256>>>(ipw);             // ctx = (Σ ctxwP)@Wv^T + bv
    k_gemm_tn<<<dim3(16, 16), 256>>>(opw, 1);           // att = ctx@Wout^T + bout
    k_combine<<<64, 256>>>(emk, strength, out);
}

// round 17
// speedup vs baseline: 1.7865x; 1.3868x over previous
#include <cuda_runtime.h>
#include <cstdint>

// Problem constants
#define BSZ 64
#define SL 512
#define EM 1024
#define NH 16
#define HDIM 64
#define QK_SCALE 0.125f   // 1/sqrt(64)

#define SC_STRIDE (BSZ * NH * SL)
#define CW_STRIDE (BSZ * NH * EM)

typedef unsigned long long ull;

__device__ __forceinline__ void ffma2(ull& d, ull a, ull b) {
    asm("fma.rn.f32x2 %0, %1, %2, %0;" : "+l"(d) : "l"(a), "l"(b));
}
__device__ __forceinline__ ull packf2(float x, float y) {
    ull r;
    asm("mov.b64 %0, {%1, %2};" : "=l"(r) : "f"(x), "f"(y));
    return r;
}
__device__ __forceinline__ float lo2(ull v) { return __uint_as_float((unsigned)v); }
__device__ __forceinline__ float hi2(ull v) { return __uint_as_float((unsigned)(v >> 32)); }

#define CP_ASYNC16(dst_u32, src_ptr) \
    asm volatile("cp.async.cg.shared.global [%0], [%1], 16;" :: "r"(dst_u32), "l"(src_ptr))
#define CP_COMMIT() asm volatile("cp.async.commit_group;")
#define CP_WAIT0()  asm volatile("cp.async.wait_group 0;" ::: "memory")

// -------- scratch (device globals; no allocations) --------
__device__ float g_qin[BSZ * EM];           // kv_src row at mask_pos
__device__ float g_orig[BSZ * EM];          // model_output row at mask_pos
__device__ float g_q[BSZ * EM];             // scale*(q_in@Wq^T + bq)
__device__ float g_qk[BSZ * NH * EM];       // q_s @ Wk (per head)
__device__ float g_scoresP[4 * SC_STRIDE];  // 4 k-quarter partial scores; attn lands in slice 0
__device__ float g_ctxwP[4 * CW_STRIDE];    // 4 s-quarter partial ctxw
__device__ float g_ctx[BSZ * EM];           // ctxw @ Wv^T + bv
__device__ float g_att[BSZ * EM];           // ctx @ Wout^T + bout

// ================= setup: mask_pos, q_in, origin_q + accumulator init =================
__global__ void k_setup(const float* __restrict__ mo, const float* __restrict__ kno,
                        const int* __restrict__ ids,
                        const int* __restrict__ pmask_id, const int* __restrict__ pknow_id,
                        const float* __restrict__ ipb, const float* __restrict__ opb) {
    __shared__ int smin;
    int b = blockIdx.x, t = threadIdx.x;
    if (t == 0) smin = SL;
    __syncthreads();
    int mid = *pmask_id;
    for (int s = t; s < SL; s += 256)
        if (ids[b * SL + s] == mid) atomicMin(&smin, s);
    __syncthreads();
    int p = (smin < SL) ? smin : 0;   // argmax of all-False -> 0
    bool isk = (ids[b * SL + p] == *pknow_id);
    const float* mrow = mo + (size_t)(b * SL + p) * EM;
    const float* krow = kno + (size_t)b * EM;
    for (int e = t; e < EM; e += 256) {
        float m = mrow[e];
        g_orig[b * EM + e] = m;
        g_qin[b * EM + e]  = isk ? krow[e] : m;
        g_q[b * EM + e]    = QK_SCALE * ipb[e];
        g_ctx[b * EM + e]  = ipb[2 * EM + e];
        g_att[b * EM + e]  = opb[e];
    }
}

// ================= TN GEMM f32x2: C[64 x 1024] += alpha * A[64x1024] @ W[1024x1024]^T
// grid (16 o-tiles, 16 k-splits), k-slice 64.
__global__ __launch_bounds__(256) void k_gemm_tn(const float* __restrict__ W, int mode) {
    __shared__ ull As2[64][33];
    __shared__ ull Ws2[64][33];
    const float* A = mode ? g_ctx : g_qin;
    float* C       = mode ? g_att : g_q;
    float alpha    = mode ? 1.0f : QK_SCALE;
    int o0 = blockIdx.x * 64;
    int kb = blockIdx.y * 64;
    int t = threadIdx.x;
    int lr = t >> 2, lc = (t & 3) << 4;  // 16 floats per thread
    {
        const float* ap = A + (size_t)lr * EM + kb + lc;
        const float* wp = W + (size_t)(o0 + lr) * EM + kb + lc;
#pragma unroll
        for (int j = 0; j < 4; j++) {
            float4 a = *(const float4*)(ap + 4 * j);
            float4 w = *(const float4*)(wp + 4 * j);
            As2[lr][(lc >> 1) + 2 * j]     = packf2(a.x, a.y);
            As2[lr][(lc >> 1) + 2 * j + 1] = packf2(a.z, a.w);
            Ws2[lr][(lc >> 1) + 2 * j]     = packf2(w.x, w.y);
            Ws2[lr][(lc >> 1) + 2 * j + 1] = packf2(w.z, w.w);
        }
    }
    __syncthreads();
    int db = t & 15, bb = t >> 4;
    ull acc[16];
#pragma unroll
    for (int i = 0; i < 16; i++) acc[i] = 0ull;
#pragma unroll 8
    for (int k2 = 0; k2 < 32; k2++) {
        ull av[4], wv[4];
#pragma unroll
        for (int i = 0; i < 4; i++) { av[i] = As2[bb + 16 * i][k2]; wv[i] = Ws2[db + 16 * i][k2]; }
#pragma unroll
        for (int i = 0; i < 4; i++)
#pragma unroll
            for (int j = 0; j < 4; j++) ffma2(acc[i * 4 + j], av[i], wv[j]);
    }
#pragma unroll
    for (int i = 0; i < 4; i++)
#pragma unroll
        for (int j = 0; j < 4; j++)
            atomicAdd(&C[(bb + 16 * i) * EM + o0 + db + 16 * j],
                      alpha * (lo2(acc[i * 4 + j]) + hi2(acc[i * 4 + j])));
}

// ================= ctx = (sum of 4 ctxw partials) @ Wv_h^T per head (f32x2) =================
// grid (16 h, 16 k-splits), k-slice 64.
__global__ __launch_bounds__(256) void k_gemm_ctx(const float* __restrict__ ipw) {
    __shared__ ull As2[64][33];
    __shared__ ull Ws2[64][33];
    int h = blockIdx.x;
    int kb = blockIdx.y * 64;
    const float* A0 = g_ctxwP + h * EM;                      // row stride NH*EM
    const float* W  = ipw + (size_t)(2 * EM + h * HDIM) * EM;
    int t = threadIdx.x;
    int lr = t >> 2, lc = (t & 3) << 4;
    {
        size_t row = (size_t)lr * (NH * EM) + kb + lc;
        float4 s0 = make_float4(0.f, 0.f, 0.f, 0.f);
        float4 s1 = s0, s2 = s0, s3 = s0;
#pragma unroll
        for (int z = 0; z < 4; z++) {
            const float* az = A0 + (size_t)z * CW_STRIDE + row;
            float4 a0 = *(const float4*)(az);
            float4 a1 = *(const float4*)(az + 4);
            float4 a2 = *(const float4*)(az + 8);
            float4 a3 = *(const float4*)(az + 12);
            s0.x += a0.x; s0.y += a0.y; s0.z += a0.z; s0.w += a0.w;
            s1.x += a1.x; s1.y += a1.y; s1.z += a1.z; s1.w += a1.w;
            s2.x += a2.x; s2.y += a2.y; s2.z += a2.z; s2.w += a2.w;
            s3.x += a3.x; s3.y += a3.y; s3.z += a3.z; s3.w += a3.w;
        }
        As2[lr][(lc >> 1)]     = packf2(s0.x, s0.y);
        As2[lr][(lc >> 1) + 1] = packf2(s0.z, s0.w);
        As2[lr][(lc >> 1) + 2] = packf2(s1.x, s1.y);
        As2[lr][(lc >> 1) + 3] = packf2(s1.z, s1.w);
        As2[lr][(lc >> 1) + 4] = packf2(s2.x, s2.y);
        As2[lr][(lc >> 1) + 5] = packf2(s2.z, s2.w);
        As2[lr][(lc >> 1) + 6] = packf2(s3.x, s3.y);
        As2[lr][(lc >> 1) + 7] = packf2(s3.z, s3.w);
        const float* wp = W + (size_t)lr * EM + kb + lc;
#pragma unroll
        for (int j = 0; j < 4; j++) {
            float4 w = *(const float4*)(wp + 4 * j);
            Ws2[lr][(lc >> 1) + 2 * j]     = packf2(w.x, w.y);
            Ws2[lr][(lc >> 1) + 2 * j + 1] = packf2(w.z, w.w);
        }
    }
    __syncthreads();
    int db = t & 15, bb = t >> 4;
    ull acc[16];
#pragma unroll
    for (int i = 0; i < 16; i++) acc[i] = 0ull;
#pragma unroll 8
    for (int k2 = 0; k2 < 32; k2++) {
        ull av[4], wv[4];
#pragma unroll
        for (int i = 0; i < 4; i++) { av[i] = As2[bb + 16 * i][k2]; wv[i] = Ws2[db + 16 * i][k2]; }
#pragma unroll
        for (int i = 0; i < 4; i++)
#pragma unroll
            for (int j = 0; j < 4; j++) ffma2(acc[i * 4 + j], av[i], wv[j]);
    }
#pragma unroll
    for (int i = 0; i < 4; i++)
#pragma unroll
        for (int j = 0; j < 4; j++)
            atomicAdd(&g_ctx[(bb + 16 * i) * EM + h * HDIM + db + 16 * j],
                      lo2(acc[i * 4 + j]) + hi2(acc[i * 4 + j]));
}

// ================= qk[b,h,e] = sum_d q_s[b,h,d] * Wk[h*64+d, e]  (f32x2 over d) =================
// grid (16 e-tiles, 16 heads), 256 thr.
__global__ __launch_bounds__(256) void k_qk(const float* __restrict__ ipw) {
    __shared__ ull As2[64][33];   // [b][d2]
    __shared__ ull Bs2[32][65];   // [d2][e]  (pair of W rows 2d2, 2d2+1)
    int e0 = blockIdx.x * 64;
    int h  = blockIdx.y;
    int t = threadIdx.x;
    // As2: 64 b-rows x 64 d
    {
        int lr = t >> 2, lc = (t & 3) << 4;
        const float* qp = g_q + (size_t)lr * EM + h * HDIM + lc;
#pragma unroll
        for (int j = 0; j < 4; j++) {
            float4 a = *(const float4*)(qp + 4 * j);
            As2[lr][(lc >> 1) + 2 * j]     = packf2(a.x, a.y);
            As2[lr][(lc >> 1) + 2 * j + 1] = packf2(a.z, a.w);
        }
    }
    // Bs2: 32 d2 x 64 e; thread: d2 = t>>3, e8 = (t&7)*8
    {
        int d2 = t >> 3, e8 = (t & 7) << 3;
        const float* w0 = ipw + (size_t)(EM + h * HDIM + 2 * d2) * EM + e0 + e8;
        const float* w1 = w0 + EM;
#pragma unroll
        for (int j = 0; j < 2; j++) {
            float4 a = *(const float4*)(w0 + 4 * j);
            float4 b = *(const float4*)(w1 + 4 * j);
            Bs2[d2][e8 + 4 * j]     = packf2(a.x, b.x);
            Bs2[d2][e8 + 4 * j + 1] = packf2(a.y, b.y);
            Bs2[d2][e8 + 4 * j + 2] = packf2(a.z, b.z);
            Bs2[d2][e8 + 4 * j + 3] = packf2(a.w, b.w);
        }
    }
    __syncthreads();
    int eb = t & 15, bb = t >> 4;
    ull acc[16];
#pragma unroll
    for (int i = 0; i < 16; i++) acc[i] = 0ull;
#pragma unroll 8
    for (int d2 = 0; d2 < 32; d2++) {
        ull av[4], wv[4];
#pragma unroll
        for (int i = 0; i < 4; i++) { av[i] = As2[bb + 16 * i][d2]; wv[i] = Bs2[d2][eb + 16 * i]; }
#pragma unroll
        for (int i = 0; i < 4; i++)
#pragma unroll
            for (int j = 0; j < 4; j++) ffma2(acc[i * 4 + j], av[i], wv[j]);
    }
#pragma unroll
    for (int i = 0; i < 4; i++)
#pragma unroll
        for (int j = 0; j < 4; j++)
            g_qk[((bb + 16 * i) * NH + h) * EM + e0 + eb + 16 * j] =
                lo2(acc[i * 4 + j]) + hi2(acc[i * 4 + j]);
}

// ================= heavy pass 1: cp.async DOUBLE-BUFFERED, 16B-swizzled kv tile =================
// partial scores over k-quarter z.  grid (64, 4, 4), 128 threads.
// kv tile: [buf][r*16 + 2*(pair ^ (r&7))], chunk = 32 k-floats (16 ull = 8 pairs).
__global__ __launch_bounds__(128) void k_scores(const float* __restrict__ mo,
                                                const float* __restrict__ kno,
                                                const int* __restrict__ ids,
                                                const int* __restrict__ pknow_id) {
    __shared__ ull kvs[2][2048];     // 32KB: [buf][128 rows x 16 ull]
    __shared__ ull qks[2][16][18];   // 4.6KB: [buf][k2][h]
    int b = blockIdx.x;
    int s0 = blockIdx.y * 128;
    int kbase = blockIdx.z * (EM / 4);
    int t = threadIdx.x;
    int kid = *pknow_id;

    int hg = (t >> 6) & 1;
    int sp = t & 63;
    ull acc[16];
#pragma unroll
    for (int i = 0; i < 16; i++) acc[i] = 0ull;

    // loader: 8 lanes per row; rows r = i*16 + rr8, pair pl = t&7
    int rr8 = t >> 3;          // 0..15
    int pl = t & 7;
    const float* knoB = kno + (size_t)b * EM;
    const float* moB  = mo + (size_t)(b * SL + s0) * EM;
    unsigned mask = 0;
#pragma unroll
    for (int i = 0; i < 8; i++)
        if (ids[b * SL + s0 + i * 16 + rr8] == kid) mask |= (1u << i);
    unsigned kv_u32 = (unsigned)__cvta_generic_to_shared(&kvs[0][0]);

    // ---- prologue: chunk 0 ----
    {
#pragma unroll
        for (int i = 0; i < 8; i++) {
            int r = i * 16 + rr8;
            const float* src = (mask >> i & 1) ? knoB : (moB + (size_t)r * EM);
            unsigned dst = kv_u32 + (unsigned)((r * 16 + 2 * (pl ^ (r & 7))) * 8);
            CP_ASYNC16(dst, src + kbase + 4 * pl);
        }
        CP_COMMIT();
        // qk chunk 0: 256 ull, 2 per thread
#pragma unroll
        for (int j = 0; j < 2; j++) {
            int i = t + 128 * j;
            int h = i >> 4, k2 = i & 15;
            qks[0][k2][h] = *(const ull*)(g_qk + (size_t)(b * NH + h) * EM + kbase + 2 * k2);
        }
        CP_WAIT0();
        __syncthreads();
    }

    for (int c = 0; c < 8; c++) {
        int buf = c & 1, nbuf = buf ^ 1;
        ull q0 = 0, q1 = 0;
        if (c < 7) {
            int k0n = kbase + (c + 1) * 32;
#pragma unroll
            for (int i = 0; i < 8; i++) {
                int r = i * 16 + rr8;
                const float* src = (mask >> i & 1) ? knoB : (moB + (size_t)r * EM);
                unsigned dst = kv_u32 + (unsigned)((nbuf * 2048 + r * 16 + 2 * (pl ^ (r & 7))) * 8);
                CP_ASYNC16(dst, src + k0n + 4 * pl);
            }
            CP_COMMIT();
            {
                int i = t;
                q0 = *(const ull*)(g_qk + (size_t)(b * NH + (i >> 4)) * EM + k0n + 2 * (i & 15));
                i = t + 128;
                q1 = *(const ull*)(g_qk + (size_t)(b * NH + (i >> 4)) * EM + k0n + 2 * (i & 15));
            }
        }
        // compute chunk c
        const ull* kvb = kvs[buf];
        int swz = sp & 7;
#pragma unroll
        for (int p = 0; p < 8; p++) {
            ulonglong2 ka2 = *(const ulonglong2*)&kvb[sp * 16 + 2 * (p ^ swz)];
            ulonglong2 kb2 = *(const ulonglong2*)&kvb[(sp + 64) * 16 + 2 * (p ^ swz)];
#pragma unroll
            for (int q = 0; q < 2; q++) {
                ull ka = q ? ka2.y : ka2.x;
                ull kb = q ? kb2.y : kb2.x;
                int k2 = 2 * p + q;
                ulonglong2 q01 = *(const ulonglong2*)&qks[buf][k2][hg * 8];
                ulonglong2 q23 = *(const ulonglong2*)&qks[buf][k2][hg * 8 + 2];
                ulonglong2 q45 = *(const ulonglong2*)&qks[buf][k2][hg * 8 + 4];
                ulonglong2 q67 = *(const ulonglong2*)&qks[buf][k2][hg * 8 + 6];
                ffma2(acc[0],  q01.x, ka); ffma2(acc[1],  q01.x, kb);
                ffma2(acc[2],  q01.y, ka); ffma2(acc[3],  q01.y, kb);
                ffma2(acc[4],  q23.x, ka); ffma2(acc[5],  q23.x, kb);
                ffma2(acc[6],  q23.y, ka); ffma2(acc[7],  q23.y, kb);
                ffma2(acc[8],  q45.x, ka); ffma2(acc[9],  q45.x, kb);
                ffma2(acc[10], q45.y, ka); ffma2(acc[11], q45.y, kb);
                ffma2(acc[12], q67.x, ka); ffma2(acc[13], q67.x, kb);
                ffma2(acc[14], q67.y, ka); ffma2(acc[15], q67.y, kb);
            }
        }
        if (c < 7) {
            qks[nbuf][t & 15][t >> 4] = q0;   // i = t
            qks[nbuf][(t + 128) & 15][(t + 128) >> 4] = q1;
            CP_WAIT0();
        }
        __syncthreads();
    }

    float* outb = g_scoresP + blockIdx.z * SC_STRIDE;
#pragma unroll
    for (int h = 0; h < 8; h++) {
        int row = (b * NH + hg * 8 + h) * SL + s0;
        outb[row + sp]      = lo2(acc[2 * h])     + hi2(acc[2 * h]);
        outb[row + sp + 64] = lo2(acc[2 * h + 1]) + hi2(acc[2 * h + 1]);
    }
}

// ================= softmax over s (512) per (b,h) row; sums the 4 k-quarter partials =================
__global__ void k_softmax() {
    int row = blockIdx.x;
    int t = threadIdx.x;
    float* p = g_scoresP + row * SL;   // slice 0: partial in, attn out
    float v[4];
#pragma unroll
    for (int i = 0; i < 4; i++) {
        int idx = row * SL + t + 128 * i;
        v[i] = g_scoresP[idx] + g_scoresP[SC_STRIDE + idx]
             + g_scoresP[2 * SC_STRIDE + idx] + g_scoresP[3 * SC_STRIDE + idx];
    }
    float m = fmaxf(fmaxf(v[0], v[1]), fmaxf(v[2], v[3]));
#pragma unroll
    for (int o = 16; o; o >>= 1) m = fmaxf(m, __shfl_xor_sync(~0u, m, o));
    __shared__ float red[4];
    if ((t & 31) == 0) red[t >> 5] = m;
    __syncthreads();
    m = fmaxf(fmaxf(red[0], red[1]), fmaxf(red[2], red[3]));
    float s = 0.f;
#pragma unroll
    for (int i = 0; i < 4; i++) { v[i] = __expf(v[i] - m); s += v[i]; }
#pragma unroll
    for (int o = 16; o; o >>= 1) s += __shfl_xor_sync(~0u, s, o);
    __syncthreads();
    if ((t & 31) == 0) red[t >> 5] = s;
    __syncthreads();
    float inv = 1.f / (red[0] + red[1] + red[2] + red[3]);
#pragma unroll
    for (int i = 0; i < 4; i++) p[t + 128 * i] = v[i] * inv;
}

// ================= heavy pass 2: cp.async DOUBLE-BUFFERED (no swizzle needed) =================
// partial ctxw over s-quarter z.  grid (64, 2, 4), 256 threads.
// kv tile: [buf][ss*256 + e2], chunk = 8 s-rows x 512 e-floats.
__global__ __launch_bounds__(256) void k_ctxw(const float* __restrict__ mo,
                                              const float* __restrict__ kno,
                                              const int* __restrict__ ids,
                                              const int* __restrict__ pknow_id) {
    __shared__ ull kvt[2][2048];    // 32KB: [buf][8 rows x 256 ull]
    __shared__ ull ps2[2][8][18];   // attn duplicated lanes
    int b = blockIdx.x;
    int e0 = blockIdx.y * 512;
    int sbase = blockIdx.z * (SL / 4);
    int t = threadIdx.x;
    int kid = *pknow_id;

    int hg = t >> 7;
    int ep = t & 127;
    ull acc[16];
#pragma unroll
    for (int i = 0; i < 16; i++) acc[i] = 0ull;

    // loader: 32 lanes per row; row lr = t>>5, float4 cols c4 = (t&31) + 32*j
    int lr = t >> 5;          // 0..7
    int c4b = t & 31;
    const float* knoB = kno + (size_t)b * EM;
    const float* moB  = mo + (size_t)(b * SL + sbase) * EM;
    unsigned mask = 0;
#pragma unroll
    for (int c = 0; c < 16; c++)
        if (ids[b * SL + sbase + c * 8 + lr] == kid) mask |= (1u << c);
    unsigned kv_u32 = (unsigned)__cvta_generic_to_shared(&kvt[0][0]);

    // ---- prologue: chunk 0 ----
    {
        const float* src = (mask & 1u) ? knoB : (moB + (size_t)lr * EM);
#pragma unroll
        for (int j = 0; j < 4; j++) {
            int c4 = c4b + 32 * j;
            unsigned dst = kv_u32 + (unsigned)((lr * 256 + 2 * c4) * 8);
            CP_ASYNC16(dst, src + e0 + 4 * c4);
        }
        CP_COMMIT();
        if (t < 128) {
            int ss = t >> 4, h = t & 15;
            float v = g_scoresP[(b * NH + h) * SL + sbase + ss];
            unsigned u = __float_as_uint(v);
            ps2[0][ss][h] = (ull)u | ((ull)u << 32);
        }
        CP_WAIT0();
        __syncthreads();
    }

    for (int c = 0; c < 16; c++) {
        int buf = c & 1, nbuf = buf ^ 1;
        ull pv = 0;
        if (c < 15) {
            int rg = (c + 1) * 8 + lr;    // row within quarter
            const float* src = (mask >> (c + 1) & 1) ? knoB : (moB + (size_t)rg * EM);
#pragma unroll
            for (int j = 0; j < 4; j++) {
                int c4 = c4b + 32 * j;
                unsigned dst = kv_u32 + (unsigned)((nbuf * 2048 + lr * 256 + 2 * c4) * 8);
                CP_ASYNC16(dst, src + e0 + 4 * c4);
            }
            CP_COMMIT();
            if (t < 128) {
                int ss = t >> 4, h = t & 15;
                float v = g_scoresP[(b * NH + h) * SL + sbase + (c + 1) * 8 + ss];
                unsigned u = __float_as_uint(v);
                pv = (ull)u | ((ull)u << 32);
            }
        }
        // compute chunk c
        const ull* kvb = kvt[buf];
#pragma unroll
        for (int ss = 0; ss < 8; ss++) {
            ull ka = kvb[ss * 256 + ep];
            ull kb = kvb[ss * 256 + ep + 128];
            ulonglong2 p01 = *(const ulonglong2*)&ps2[buf][ss][hg * 8];
            ulonglong2 p23 = *(const ulonglong2*)&ps2[buf][ss][hg * 8 + 2];
            ulonglong2 p45 = *(const ulonglong2*)&ps2[buf][ss][hg * 8 + 4];
            ulonglong2 p67 = *(const ulonglong2*)&ps2[buf][ss][hg * 8 + 6];
            ffma2(acc[0],  p01.x, ka); ffma2(acc[1],  p01.x, kb);
            ffma2(acc[2],  p01.y, ka); ffma2(acc[3],  p01.y, kb);
            ffma2(acc[4],  p23.x, ka); ffma2(acc[5],  p23.x, kb);
            ffma2(acc[6],  p23.y, ka); ffma2(acc[7],  p23.y, kb);
            ffma2(acc[8],  p45.x, ka); ffma2(acc[9],  p45.x, kb);
            ffma2(acc[10], p45.y, ka); ffma2(acc[11], p45.y, kb);
            ffma2(acc[12], p67.x, ka); ffma2(acc[13], p67.x, kb);
            ffma2(acc[14], p67.y, ka); ffma2(acc[15], p67.y, kb);
        }
        if (c < 15) {
            if (t < 128) ps2[nbuf][t >> 4][t & 15] = pv;
            CP_WAIT0();
        }
        __syncthreads();
    }

    float* outb = g_ctxwP + blockIdx.z * CW_STRIDE;
#pragma unroll
    for (int h = 0; h < 8; h++) {
        size_t g = (size_t)(b * NH + hg * 8 + h) * EM + e0;
        *(ull*)&outb[g + 2 * ep]         = acc[2 * h];
        *(ull*)&outb[g + 2 * (ep + 128)] = acc[2 * h + 1];
    }
}

// ================= final combine (+ robust bool-dtype detection) =================
__global__ void k_combine(const unsigned char* __restrict__ emk,
                          const float* __restrict__ strength,
                          float* __restrict__ out) {
    __shared__ int mode;  // 0=int32, 1=uint8, 2=float32
    int b = blockIdx.x, t = threadIdx.x;
    if (t == 0) {
        const unsigned* pw = (const unsigned*)emk;
        int isf = 0, isu = 0;
        for (int w = 0; w < 16; ++w) if (pw[w] == 0x3F800000u) isf = 1;
        if (!isf)
            for (int j = 0; j < 64; ++j) if ((j & 3) && emk[j]) isu = 1;
        mode = isf ? 2 : (isu ? 1 : 0);
    }
    __syncthreads();
    bool empty;
    if (mode == 1)      empty = emk[b] != 0;
    else if (mode == 2) empty = ((const unsigned*)emk)[b] != 0;
    else                empty = ((const int*)emk)[b] != 0;
    float st = *strength;
    for (int o = t; o < EM; o += 256) {
        float og = g_orig[b * EM + o];
        out[b * EM + o] = empty ? og : og + st * g_att[b * EM + o];
    }
}

extern "C" void kernel_launch(void* const* d_in, const int* in_sizes, int n_in,
                              void* d_out, int out_size) {
    const float* mo       = (const float*)d_in[0];
    const float* kno      = (const float*)d_in[1];
    const float* ipw      = (const float*)d_in[2];
    const float* ipb      = (const float*)d_in[3];
    const float* opw      = (const float*)d_in[4];
    const float* opb      = (const float*)d_in[5];
    const float* strength = (const float*)d_in[6];
    const int*   ids      = (const int*)d_in[7];
    const unsigned char* emk = (const unsigned char*)d_in[8];
    const int*   kid      = (const int*)d_in[9];
    const int*   midp     = (const int*)d_in[10];
    float* out = (float*)d_out;

    k_setup<<<64, 256>>>(mo, kno, ids, midp, kid, ipb, opb);
    k_gemm_tn<<<dim3(16, 16), 256>>>(ipw, 0);           // q = scale*(q_in@Wq^T + bq)
    k_qk<<<dim3(16, 16), 256>>>(ipw);                   // qk = q_s @ Wk per head
    k_scores<<<dim3(64, 4, 4), 128>>>(mo, kno, ids, kid);
    k_softmax<<<BSZ * NH, 128>>>();
    k_ctxw<<<dim3(64, 2, 4), 256>>>(mo, kno, ids, kid);
    k_gemm_ctx<<<dim3(16, 16), 256>>>(ipw);             // ctx = (Σ ctxwP)@Wv^T + bv
    k_gemm_tn<<<dim3(16, 16), 256>>>(opw, 1);           // att = ctx@Wout^T + bout
    k_combine<<<64, 256>>>(emk, strength, out);
}